// round 4
// baseline (speedup 1.0000x reference)
#include <cuda_runtime.h>
#include <math.h>

#define Bq   2
#define Nn   2048
#define Dd   256
#define Hh   4
#define DHd  64
#define Jj   32
#define FFf  4
#define Mm   16
#define HID  274
#define HP   288            // padded hidden dim (cols 274..287 zero)
#define QKVC (3*Hh*DHd)     // 768
#define NODES (Bq*Nn)       // 4096

typedef unsigned long long ull;

// ---------------- f32x2 packed helpers ----------------
__device__ __forceinline__ ull fma2(ull a, ull b, ull c) {
    ull d;
    asm("fma.rn.f32x2 %0, %1, %2, %3;" : "=l"(d) : "l"(a), "l"(b), "l"(c));
    return d;
}
__device__ __forceinline__ ull add2(ull a, ull b) {
    ull d;
    asm("add.rn.f32x2 %0, %1, %2;" : "=l"(d) : "l"(a), "l"(b));
    return d;
}
__device__ __forceinline__ ull pack2(float lo, float hi) {
    ull d;
    asm("mov.b64 %0, {%1, %2};" : "=l"(d) : "f"(lo), "f"(hi));
    return d;
}
__device__ __forceinline__ void unpack2(ull v, float& lo, float& hi) {
    asm("mov.b64 {%0, %1}, %2;" : "=f"(lo), "=f"(hi) : "l"(v));
}

// ---------------- scratch ----------------
__device__ float g_qkv [Bq*Nn*QKVC];
__device__ float g_q1  [Bq*Nn*Hh*HP];
__device__ float g_k1  [Bq*Nn*Hh*HP];
__device__ float g_sim [Bq*Hh*Nn*Jj];
__device__ float g_cw  [Bq*Hh*Nn*Jj];
__device__ float g_outh[Bq*Nn*Dd];

// ---------------- 64x64 tiled SGEMM with FFMA2 inner product ----------------
__global__ void gemm_tile(const float* __restrict__ A, const float* __restrict__ Bm,
                          const float* __restrict__ bias, float* __restrict__ C,
                          int M, int N, int K)
{
    __shared__ float As[16*68];
    __shared__ float Bs[16*68];
    int tid = threadIdx.x;
    int tx = tid & 15, ty = tid >> 4;
    int rowBase = blockIdx.y * 64;
    int colBase = blockIdx.x * 64;
    ull acc2[4][2];
    #pragma unroll
    for (int r = 0; r < 4; r++) { acc2[r][0] = pack2(0.f,0.f); acc2[r][1] = acc2[r][0]; }

    for (int k0 = 0; k0 < K; k0 += 16) {
        for (int i = tid; i < 1024; i += 256) {
            int r = i >> 4, kk = i & 15;
            As[kk*68 + r] = A[(long)(rowBase + r) * K + k0 + kk];
        }
        for (int i = tid; i < 1024; i += 256) {
            int kk = i >> 6, c = i & 63;
            Bs[kk*68 + c] = Bm[(long)(k0 + kk) * N + colBase + c];
        }
        __syncthreads();
        #pragma unroll
        for (int kk = 0; kk < 16; kk++) {
            float4 av = *(float4*)&As[kk*68 + ty*4];
            ulonglong2 bv = *(ulonglong2*)&Bs[kk*68 + tx*4];
            ull a0 = pack2(av.x, av.x);
            ull a1 = pack2(av.y, av.y);
            ull a2 = pack2(av.z, av.z);
            ull a3 = pack2(av.w, av.w);
            acc2[0][0] = fma2(a0, bv.x, acc2[0][0]); acc2[0][1] = fma2(a0, bv.y, acc2[0][1]);
            acc2[1][0] = fma2(a1, bv.x, acc2[1][0]); acc2[1][1] = fma2(a1, bv.y, acc2[1][1]);
            acc2[2][0] = fma2(a2, bv.x, acc2[2][0]); acc2[2][1] = fma2(a2, bv.y, acc2[2][1]);
            acc2[3][0] = fma2(a3, bv.x, acc2[3][0]); acc2[3][1] = fma2(a3, bv.y, acc2[3][1]);
        }
        __syncthreads();
    }
    #pragma unroll
    for (int r = 0; r < 4; r++) {
        int row = rowBase + ty*4 + r;
        float c0,c1,c2,c3;
        unpack2(acc2[r][0], c0, c1);
        unpack2(acc2[r][1], c2, c3);
        int col = colBase + tx*4;
        if (bias) { c0 += bias[col]; c1 += bias[col+1]; c2 += bias[col+2]; c3 += bias[col+3]; }
        C[(long)row * N + col]     = c0;
        C[(long)row * N + col + 1] = c1;
        C[(long)row * N + col + 2] = c2;
        C[(long)row * N + col + 3] = c3;
    }
}

// ---------------- q1/k1 precompute with FFMA2 ----------------
__global__ void __launch_bounds__(256,1) qk1_kernel(
    const float* __restrict__ qkv, const float* __restrict__ w_e1,
    float* __restrict__ q1, float* __restrict__ k1)
{
    extern __shared__ float sm[];
    float* sWq = sm;             // [64][HP]
    float* sWk = sWq + 64*HP;    // [64][HP]
    float* sAq = sWk + 64*HP;    // [16][256]
    float* sAk = sAq + 16*256;   // [16][256]
    int tid = threadIdx.x;
    int node0 = blockIdx.x * 16;

    for (int i = tid; i < 64*HP; i += 256) {
        int r = i / HP, o = i - r*HP;
        sWq[i] = (o < HID) ? w_e1[r*HID + o] : 0.f;
        sWk[i] = (o < HID) ? w_e1[(64 + r)*HID + o] : 0.f;
    }
    for (int i = tid; i < 4096; i += 256) {
        int t = i >> 8, c = i & 255;
        sAq[i] = qkv[(long)(node0 + t)*QKVC + c];
        sAk[i] = qkv[(long)(node0 + t)*QKVC + 256 + c];
    }
    __syncthreads();

    int ty = tid >> 4, tx = tid & 15;
    for (int pass = 0; pass < 2; pass++) {
        const float* A = pass ? sAk : sAq;
        const float* W = pass ? sWk : sWq;
        float* Cg = pass ? k1 : q1;
        ull acc2[4][9];
        #pragma unroll
        for (int r = 0; r < 4; r++)
            #pragma unroll
            for (int c = 0; c < 9; c++) acc2[r][c] = pack2(0.f,0.f);
        #pragma unroll 4
        for (int i = 0; i < 64; i++) {
            ull a2[4];
            #pragma unroll
            for (int r = 0; r < 4; r++) {
                float a = A[ty*256 + r*64 + i];
                a2[r] = pack2(a, a);
            }
            #pragma unroll
            for (int c = 0; c < 9; c++) {
                ull w2 = pack2(W[i*HP + tx + 16*(2*c)], W[i*HP + tx + 16*(2*c+1)]);
                #pragma unroll
                for (int r = 0; r < 4; r++) acc2[r][c] = fma2(a2[r], w2, acc2[r][c]);
            }
        }
        #pragma unroll
        for (int r = 0; r < 4; r++) {
            long grow = (long)(node0 + ty)*4 + r;
            #pragma unroll
            for (int c = 0; c < 9; c++) {
                float v0, v1;
                unpack2(acc2[r][c], v0, v1);
                Cg[grow*HP + tx + 16*(2*c)]   = v0;
                Cg[grow*HP + tx + 16*(2*c+1)] = v1;
            }
        }
    }
}

// ---------------- edge_flat v2: FFMA2 throughout ----------------
__global__ void __launch_bounds__(256) edge_flat(
    const float* __restrict__ q1, const float* __restrict__ k1,
    const float* __restrict__ coors, const int* __restrict__ nbhd,
    const float* __restrict__ w_e1, const float* __restrict__ b_e1,
    const float* __restrict__ w_e2, const float* __restrict__ b_e2,
    const float* __restrict__ w_a1, const float* __restrict__ b_a1,
    const float* __restrict__ w_a2, const float* __restrict__ b_a2,
    const float* __restrict__ w_c1, const float* __restrict__ b_c1,
    const float* __restrict__ w_c2, const float* __restrict__ b_c2,
    float* __restrict__ simo, float* __restrict__ cwo)
{
    extern __shared__ float sm[];
    float* sWr  = sm;               // [9][HP]
    float* sW2  = sWr + 9*HP;       // [HP][16]  (i-major, natural w_e2 layout)
    float* sB1  = sW2 + HP*16;      // [HP]
    float* sQ1  = sB1 + HP;         // [4][HP]
    float* sA1  = sQ1 + 4*HP;       // [16][64]
    float* sC1  = sA1 + 1024;       // [16][64]
    float* sBa  = sC1 + 1024;       // [64]
    float* sBc  = sBa + 64;         // [64]
    float* sA2  = sBc + 64;         // [64]
    float* sC2  = sA2 + 64;         // [64]
    float* sB2  = sC2 + 64;         // [16]
    float* sScal= sB2 + 16;         // [4]
    int*   sIdx = (int*)(sScal + 4);// [32]

    int tid = threadIdx.x;
    int bn  = blockIdx.x;
    int bB  = bn >> 11;
    int nn  = bn & (Nn - 1);

    for (int i = tid; i < 9*HP; i += 256) {
        int f = i / HP, o = i - f*HP;
        sWr[i] = (o < HID) ? w_e1[(128 + f)*HID + o] : 0.f;
    }
    for (int i = tid; i < HP*16; i += 256)
        sW2[i] = (i < HID*16) ? w_e2[i] : 0.f;
    for (int i = tid; i < HP; i += 256) sB1[i] = (i < HID) ? b_e1[i] : 0.f;
    for (int i = tid; i < 4*HP; i += 256) sQ1[i] = q1[(long)bn*4*HP + i];
    for (int i = tid; i < 1024; i += 256) { sA1[i] = w_a1[i]; sC1[i] = w_c1[i]; }
    if (tid < 64) { sBa[tid] = b_a1[tid]; sBc[tid] = b_c1[tid];
                    sA2[tid] = w_a2[tid]; sC2[tid] = w_c2[tid]; }
    if (tid < 16) sB2[tid] = b_e2[tid];
    if (tid == 0) { sScal[0] = b_a2[0]; sScal[1] = b_c2[0]; }
    if (tid < 32) sIdx[tid] = nbhd[bn*Jj + tid];
    __syncthreads();

    int w = tid >> 5, lane = tid & 31;
    int qq = lane >> 3, s = lane & 7;
    int j = w*4 + qq;
    int idx = sIdx[j];
    long krow = ((long)(bB*Nn + idx)*4) * HP;

    // rel_enc via 8-lane split
    float dx = coors[bn*3+0] - coors[(bB*Nn+idx)*3+0];
    float dy = coors[bn*3+1] - coors[(bB*Nn+idx)*3+1];
    float dz = coors[bn*3+2] - coors[(bB*Nn+idx)*3+2];
    float x = dx*dx + dy*dy + dz*dz;
    float xs = x / (float)(1 << (s & 3));
    float sv = sinf(xs), cv = cosf(xs);
    float myre = (s < 4) ? sv : cv;
    ull re2[9];
    #pragma unroll
    for (int f = 0; f < 8; f++) {
        float r = __shfl_sync(0xffffffffu, myre, f, 8);
        re2[f] = pack2(r, r);
    }
    re2[8] = pack2(x, x);

    ull acc2[4][8];
    #pragma unroll
    for (int h = 0; h < 4; h++)
        #pragma unroll
        for (int t2 = 0; t2 < 8; t2++) acc2[h][t2] = pack2(0.f, 0.f);

    #pragma unroll 3
    for (int r = 0; r < 9; r++) {
        int i0 = (s + 8*r) * 4;
        // r1 (packed over i-pairs)
        ulonglong2 bseed = *(ulonglong2*)&sB1[i0];
        ull r1a = bseed.x, r1b = bseed.y;
        #pragma unroll
        for (int f = 0; f < 9; f++) {
            ulonglong2 wv = *(ulonglong2*)&sWr[f*HP + i0];
            r1a = fma2(re2[f], wv.x, r1a);
            r1b = fma2(re2[f], wv.y, r1b);
        }
        // hv scalars for 4 heads x 4 i
        float hvs[4][4];
        #pragma unroll
        for (int h = 0; h < 4; h++) {
            ulonglong2 q2 = *(ulonglong2*)&sQ1[h*HP + i0];
            ulonglong2 k2 = *(const ulonglong2*)&k1[krow + h*HP + i0];
            ull s01 = add2(add2(q2.x, k2.x), r1a);
            ull s23 = add2(add2(q2.y, k2.y), r1b);
            float h0,h1,h2,h3;
            unpack2(s01, h0, h1);
            unpack2(s23, h2, h3);
            hvs[h][0] = fmaxf(h0, 0.f); hvs[h][1] = fmaxf(h1, 0.f);
            hvs[h][2] = fmaxf(h2, 0.f); hvs[h][3] = fmaxf(h3, 0.f);
        }
        // layer2: per i, W2 row loaded once, reused by all 4 heads
        #pragma unroll
        for (int ii = 0; ii < 4; ii++) {
            const ulonglong2* w2r = (const ulonglong2*)&sW2[(i0 + ii)*16];
            ulonglong2 wv0 = w2r[0], wv1 = w2r[1], wv2 = w2r[2], wv3 = w2r[3];
            ull hb0 = pack2(hvs[0][ii], hvs[0][ii]);
            ull hb1 = pack2(hvs[1][ii], hvs[1][ii]);
            ull hb2 = pack2(hvs[2][ii], hvs[2][ii]);
            ull hb3 = pack2(hvs[3][ii], hvs[3][ii]);
            acc2[0][0]=fma2(hb0,wv0.x,acc2[0][0]); acc2[0][1]=fma2(hb0,wv0.y,acc2[0][1]);
            acc2[0][2]=fma2(hb0,wv1.x,acc2[0][2]); acc2[0][3]=fma2(hb0,wv1.y,acc2[0][3]);
            acc2[0][4]=fma2(hb0,wv2.x,acc2[0][4]); acc2[0][5]=fma2(hb0,wv2.y,acc2[0][5]);
            acc2[0][6]=fma2(hb0,wv3.x,acc2[0][6]); acc2[0][7]=fma2(hb0,wv3.y,acc2[0][7]);
            acc2[1][0]=fma2(hb1,wv0.x,acc2[1][0]); acc2[1][1]=fma2(hb1,wv0.y,acc2[1][1]);
            acc2[1][2]=fma2(hb1,wv1.x,acc2[1][2]); acc2[1][3]=fma2(hb1,wv1.y,acc2[1][3]);
            acc2[1][4]=fma2(hb1,wv2.x,acc2[1][4]); acc2[1][5]=fma2(hb1,wv2.y,acc2[1][5]);
            acc2[1][6]=fma2(hb1,wv3.x,acc2[1][6]); acc2[1][7]=fma2(hb1,wv3.y,acc2[1][7]);
            acc2[2][0]=fma2(hb2,wv0.x,acc2[2][0]); acc2[2][1]=fma2(hb2,wv0.y,acc2[2][1]);
            acc2[2][2]=fma2(hb2,wv1.x,acc2[2][2]); acc2[2][3]=fma2(hb2,wv1.y,acc2[2][3]);
            acc2[2][4]=fma2(hb2,wv2.x,acc2[2][4]); acc2[2][5]=fma2(hb2,wv2.y,acc2[2][5]);
            acc2[2][6]=fma2(hb2,wv3.x,acc2[2][6]); acc2[2][7]=fma2(hb2,wv3.y,acc2[2][7]);
            acc2[3][0]=fma2(hb3,wv0.x,acc2[3][0]); acc2[3][1]=fma2(hb3,wv0.y,acc2[3][1]);
            acc2[3][2]=fma2(hb3,wv1.x,acc2[3][2]); acc2[3][3]=fma2(hb3,wv1.y,acc2[3][3]);
            acc2[3][4]=fma2(hb3,wv2.x,acc2[3][4]); acc2[3][5]=fma2(hb3,wv2.y,acc2[3][5]);
            acc2[3][6]=fma2(hb3,wv3.x,acc2[3][6]); acc2[3][7]=fma2(hb3,wv3.y,acc2[3][7]);
        }
    }

    // butterfly reduce over 8-lane group (packed adds)
    #pragma unroll
    for (int h = 0; h < 4; h++)
        #pragma unroll
        for (int t2 = 0; t2 < 8; t2++) {
            ull v = acc2[h][t2];
            v = add2(v, __shfl_xor_sync(0xffffffffu, v, 1));
            v = add2(v, __shfl_xor_sync(0xffffffffu, v, 2));
            v = add2(v, __shfl_xor_sync(0xffffffffu, v, 4));
            acc2[h][t2] = v;
        }

    // branch task per lane: h = s>>1, br = s&1
    int hh = s >> 1, br = s & 1;
    ull mvp[16];
    #pragma unroll
    for (int t2 = 0; t2 < 8; t2++) {
        ull v01 = (hh & 1) ? acc2[1][t2] : acc2[0][t2];
        ull v23 = (hh & 1) ? acc2[3][t2] : acc2[2][t2];
        ull v = (hh & 2) ? v23 : v01;
        float m0, m1;
        unpack2(v, m0, m1);
        m0 = fmaxf(m0 + sB2[2*t2],   0.f);
        m1 = fmaxf(m1 + sB2[2*t2+1], 0.f);
        mvp[2*t2]   = pack2(m0, m0);
        mvp[2*t2+1] = pack2(m1, m1);
    }
    const float* w1 = br ? sC1 : sA1;
    const float* w2 = br ? sC2 : sA2;
    const float* bb = br ? sBc : sBa;
    ull dacc = pack2(0.f, 0.f);
    #pragma unroll 4
    for (int u4 = 0; u4 < 16; u4++) {
        ulonglong2 hv = *(const ulonglong2*)&bb[u4*4];
        ull h01 = hv.x, h23 = hv.y;
        #pragma unroll
        for (int t = 0; t < 16; t++) {
            ulonglong2 wv = *(const ulonglong2*)&w1[t*64 + u4*4];
            h01 = fma2(mvp[t], wv.x, h01);
            h23 = fma2(mvp[t], wv.y, h23);
        }
        float a0,a1,a2b,a3;
        unpack2(h01, a0, a1);
        unpack2(h23, a2b, a3);
        a0 = fmaxf(a0, 0.f); a1 = fmaxf(a1, 0.f);
        a2b = fmaxf(a2b, 0.f); a3 = fmaxf(a3, 0.f);
        ulonglong2 w2v = *(const ulonglong2*)&w2[u4*4];
        dacc = fma2(pack2(a0, a1),  w2v.x, dacc);
        dacc = fma2(pack2(a2b, a3), w2v.y, dacc);
    }
    float d0, d1;
    unpack2(dacc, d0, d1);
    float bacc = d0 + d1;

    long e = ((long)(bB*Hh + hh)*Nn + nn)*Jj + j;
    float val = bacc + (br ? sScal[1] : sScal[0]);
    (br ? cwo : simo)[e] = val;
}

// ---------------- softmax over j, out = attn@v_nb, coors_out ----------------
__global__ void attend_kernel(const float* __restrict__ qkv,
                              const float* __restrict__ simi, const float* __restrict__ cwi,
                              const int* __restrict__ nbhd, const float* __restrict__ basis,
                              float* __restrict__ outh, float* __restrict__ coors_out)
{
    int bn = blockIdx.x;
    int b = bn / Nn, n = bn % Nn;
    int w = threadIdx.x >> 5, lane = threadIdx.x & 31;
    int idx = nbhd[bn*Jj + lane];

    float s = simi[((long)((b*Hh + w)*Nn + n))*Jj + lane];
    float mx = s;
    #pragma unroll
    for (int o = 16; o; o >>= 1) mx = fmaxf(mx, __shfl_xor_sync(0xffffffffu, mx, o));
    float e = expf(s - mx);
    float sum = e;
    #pragma unroll
    for (int o = 16; o; o >>= 1) sum += __shfl_xor_sync(0xffffffffu, sum, o);
    float attn = e / sum;

    float acc0 = 0.f, acc1 = 0.f;
    #pragma unroll
    for (int j = 0; j < Jj; j++) {
        float a = __shfl_sync(0xffffffffu, attn, j);
        int ij  = __shfl_sync(0xffffffffu, idx,  j);
        const float* vr = qkv + (long)(b*Nn + ij)*QKVC + 2*Hh*DHd + w*DHd;
        acc0 += a * vr[lane];
        acc1 += a * vr[lane + 32];
    }
    outh[(long)bn*Dd + w*DHd + lane]      = acc0;
    outh[(long)bn*Dd + w*DHd + lane + 32] = acc1;

    if (w == 0) {
        float cwt = 0.f;
        #pragma unroll
        for (int hh = 0; hh < Hh; hh++)
            cwt += cwi[((long)((b*Hh + hh)*Nn + n))*Jj + lane];
        const float* brow = basis + ((long)(b*Nn + n)*Nn + idx)*3;
        float cx = cwt*brow[0], cy = cwt*brow[1], cz = cwt*brow[2];
        #pragma unroll
        for (int o = 16; o; o >>= 1) {
            cx += __shfl_xor_sync(0xffffffffu, cx, o);
            cy += __shfl_xor_sync(0xffffffffu, cy, o);
            cz += __shfl_xor_sync(0xffffffffu, cz, o);
        }
        if (lane == 0) {
            coors_out[bn*3+0] = cx;
            coors_out[bn*3+1] = cy;
            coors_out[bn*3+2] = cz;
        }
    }
}

// ---------------- launch ----------------
extern "C" void kernel_launch(void* const* d_in, const int* in_sizes, int n_in,
                              void* d_out, int out_size)
{
    const float* feats  = (const float*)d_in[0];
    const float* coors  = (const float*)d_in[1];
    const float* basis  = (const float*)d_in[2];
    const int*   nbhd   = (const int*)  d_in[3];
    const float* w_qkv  = (const float*)d_in[4];
    const float* w_out  = (const float*)d_in[5];
    const float* b_out  = (const float*)d_in[6];
    const float* w_e1   = (const float*)d_in[7];
    const float* b_e1   = (const float*)d_in[8];
    const float* w_e2   = (const float*)d_in[9];
    const float* b_e2   = (const float*)d_in[10];
    const float* w_a1   = (const float*)d_in[11];
    const float* b_a1   = (const float*)d_in[12];
    const float* w_a2   = (const float*)d_in[13];
    const float* b_a2   = (const float*)d_in[14];
    const float* w_c1   = (const float*)d_in[15];
    const float* b_c1   = (const float*)d_in[16];
    const float* w_c2   = (const float*)d_in[17];
    const float* b_c2   = (const float*)d_in[18];

    float* out       = (float*)d_out;
    float* coors_out = out + (long)Bq*Nn*Dd;

    void* p;
    cudaGetSymbolAddress(&p, g_qkv);  float* qkv  = (float*)p;
    cudaGetSymbolAddress(&p, g_q1);   float* q1   = (float*)p;
    cudaGetSymbolAddress(&p, g_k1);   float* k1   = (float*)p;
    cudaGetSymbolAddress(&p, g_sim);  float* simv = (float*)p;
    cudaGetSymbolAddress(&p, g_cw);   float* cwv  = (float*)p;
    cudaGetSymbolAddress(&p, g_outh); float* outh = (float*)p;

    // 1) qkv = feats @ w_qkv
    gemm_tile<<<dim3(QKVC/64, (Bq*Nn)/64), 256>>>(feats, w_qkv, nullptr, qkv,
                                                  Bq*Nn, QKVC, Dd);

    // 2) q1/k1 tables
    const int smemQK = (64*HP*2 + 16*256*2) * 4;
    cudaFuncSetAttribute(qk1_kernel, cudaFuncAttributeMaxDynamicSharedMemorySize, smemQK);
    qk1_kernel<<<256, 256, smemQK>>>(qkv, w_e1, q1, k1);

    // 3) edge_flat
    const int smemE = (9*HP + HP*16 + HP + 4*HP + 1024 + 1024 + 64*4 + 16 + 4 + 32) * 4;
    cudaFuncSetAttribute(edge_flat, cudaFuncAttributeMaxDynamicSharedMemorySize, smemE);
    edge_flat<<<NODES, 256, smemE>>>(q1, k1, coors, nbhd,
        w_e1, b_e1, w_e2, b_e2, w_a1, b_a1, w_a2, b_a2, w_c1, b_c1, w_c2, b_c2,
        simv, cwv);

    // 4) softmax + v-gather + coors einsum
    attend_kernel<<<Bq*Nn, 128>>>(qkv, simv, cwv, nbhd, basis, outh, coors_out);

    // 5) out = outh @ w_out + b_out
    gemm_tile<<<dim3(Dd/64, (Bq*Nn)/64), 256>>>(outh, w_out, b_out, out,
                                                Bq*Nn, Dd, Dd);
}

// round 5
// speedup vs baseline: 1.0440x; 1.0440x over previous
#include <cuda_runtime.h>
#include <math.h>

#define Bq   2
#define Nn   2048
#define Dd   256
#define Hh   4
#define DHd  64
#define Jj   32
#define FFf  4
#define Mm   16
#define HID  274
#define HP   288            // padded hidden dim (cols 274..287 zero)
#define QKVC (3*Hh*DHd)     // 768
#define NODES (Bq*Nn)       // 4096

typedef unsigned long long ull;

// ---------------- f32x2 packed helpers ----------------
__device__ __forceinline__ ull fma2(ull a, ull b, ull c) {
    ull d;
    asm("fma.rn.f32x2 %0, %1, %2, %3;" : "=l"(d) : "l"(a), "l"(b), "l"(c));
    return d;
}
__device__ __forceinline__ ull add2(ull a, ull b) {
    ull d;
    asm("add.rn.f32x2 %0, %1, %2;" : "=l"(d) : "l"(a), "l"(b));
    return d;
}
__device__ __forceinline__ ull pack2(float lo, float hi) {
    ull d;
    asm("mov.b64 %0, {%1, %2};" : "=l"(d) : "f"(lo), "f"(hi));
    return d;
}
__device__ __forceinline__ void unpack2(ull v, float& lo, float& hi) {
    asm("mov.b64 {%0, %1}, %2;" : "=f"(lo), "=f"(hi) : "l"(v));
}

// ---------------- scratch ----------------
__device__ float g_qkv [Bq*Nn*QKVC];
__device__ float g_q1  [Bq*Nn*Hh*HP];
__device__ float g_k1  [Bq*Nn*Hh*HP];
__device__ float g_sim [Bq*Hh*Nn*Jj];
__device__ float g_cw  [Bq*Hh*Nn*Jj];
__device__ float g_outh[Bq*Nn*Dd];

// ---------------- generic 64x64 tiled SGEMM, C = A@B (+bias)  [round-3 scalar] ----------------
__global__ void gemm_tile(const float* __restrict__ A, const float* __restrict__ Bm,
                          const float* __restrict__ bias, float* __restrict__ C,
                          int M, int N, int K)
{
    __shared__ float As[16][65];
    __shared__ float Bs[16][65];
    int tid = threadIdx.x;
    int tx = tid & 15, ty = tid >> 4;
    int rowBase = blockIdx.y * 64;
    int colBase = blockIdx.x * 64;
    float acc[4][4] = {};
    for (int k0 = 0; k0 < K; k0 += 16) {
        for (int i = tid; i < 1024; i += 256) {
            int r = i >> 4, kk = i & 15;
            As[kk][r] = A[(long)(rowBase + r) * K + k0 + kk];
        }
        for (int i = tid; i < 1024; i += 256) {
            int kk = i >> 6, c = i & 63;
            Bs[kk][c] = Bm[(long)(k0 + kk) * N + colBase + c];
        }
        __syncthreads();
        #pragma unroll
        for (int kk = 0; kk < 16; kk++) {
            float a[4], bb[4];
            #pragma unroll
            for (int r = 0; r < 4; r++) a[r] = As[kk][ty*4 + r];
            #pragma unroll
            for (int c = 0; c < 4; c++) bb[c] = Bs[kk][tx*4 + c];
            #pragma unroll
            for (int r = 0; r < 4; r++)
                #pragma unroll
                for (int c = 0; c < 4; c++)
                    acc[r][c] += a[r] * bb[c];
        }
        __syncthreads();
    }
    #pragma unroll
    for (int r = 0; r < 4; r++) {
        int row = rowBase + ty*4 + r;
        #pragma unroll
        for (int c = 0; c < 4; c++) {
            int col = colBase + tx*4 + c;
            float v = acc[r][c];
            if (bias) v += bias[col];
            C[(long)row * N + col] = v;
        }
    }
}

// ---------------- q1/k1 precompute  [round-3 scalar] ----------------
__global__ void __launch_bounds__(256,1) qk1_kernel(
    const float* __restrict__ qkv, const float* __restrict__ w_e1,
    float* __restrict__ q1, float* __restrict__ k1)
{
    extern __shared__ float sm[];
    float* sWq = sm;             // [64][HP]
    float* sWk = sWq + 64*HP;    // [64][HP]
    float* sAq = sWk + 64*HP;    // [16][256]
    float* sAk = sAq + 16*256;   // [16][256]
    int tid = threadIdx.x;
    int node0 = blockIdx.x * 16;

    for (int i = tid; i < 64*HP; i += 256) {
        int r = i / HP, o = i - r*HP;
        sWq[i] = (o < HID) ? w_e1[r*HID + o] : 0.f;
        sWk[i] = (o < HID) ? w_e1[(64 + r)*HID + o] : 0.f;
    }
    for (int i = tid; i < 4096; i += 256) {
        int t = i >> 8, c = i & 255;
        sAq[i] = qkv[(long)(node0 + t)*QKVC + c];
        sAk[i] = qkv[(long)(node0 + t)*QKVC + 256 + c];
    }
    __syncthreads();

    int ty = tid >> 4, tx = tid & 15;
    for (int pass = 0; pass < 2; pass++) {
        const float* A = pass ? sAk : sAq;
        const float* W = pass ? sWk : sWq;
        float* Cg = pass ? k1 : q1;
        float acc[4][18];
        #pragma unroll
        for (int r = 0; r < 4; r++)
            #pragma unroll
            for (int c = 0; c < 18; c++) acc[r][c] = 0.f;
        #pragma unroll 4
        for (int i = 0; i < 64; i++) {
            float a[4];
            #pragma unroll
            for (int r = 0; r < 4; r++) a[r] = A[ty*256 + r*64 + i];
            #pragma unroll
            for (int c = 0; c < 18; c++) {
                float w = W[i*HP + tx + 16*c];
                #pragma unroll
                for (int r = 0; r < 4; r++) acc[r][c] += a[r] * w;
            }
        }
        #pragma unroll
        for (int r = 0; r < 4; r++) {
            long grow = (long)(node0 + ty)*4 + r;
            #pragma unroll
            for (int c = 0; c < 18; c++)
                Cg[grow*HP + tx + 16*c] = acc[r][c];
        }
    }
}

// ---------------- edge_flat: scalar r1, f32x2 layer2+branch, reg-capped ----------------
__global__ void __launch_bounds__(256, 2) edge_flat(
    const float* __restrict__ q1, const float* __restrict__ k1,
    const float* __restrict__ coors, const int* __restrict__ nbhd,
    const float* __restrict__ w_e1, const float* __restrict__ b_e1,
    const float* __restrict__ w_e2, const float* __restrict__ b_e2,
    const float* __restrict__ w_a1, const float* __restrict__ b_a1,
    const float* __restrict__ w_a2, const float* __restrict__ b_a2,
    const float* __restrict__ w_c1, const float* __restrict__ b_c1,
    const float* __restrict__ w_c2, const float* __restrict__ b_c2,
    float* __restrict__ simo, float* __restrict__ cwo)
{
    extern __shared__ float sm[];
    float* sWr  = sm;               // [9][HP]
    float* sW2  = sWr + 9*HP;       // [HP][16]  (i-major, natural w_e2 layout)
    float* sB1  = sW2 + HP*16;      // [HP]
    float* sQ1  = sB1 + HP;         // [4][HP]
    float* sA1  = sQ1 + 4*HP;       // [16][64]
    float* sC1  = sA1 + 1024;       // [16][64]
    float* sBa  = sC1 + 1024;       // [64]
    float* sBc  = sBa + 64;         // [64]
    float* sA2  = sBc + 64;         // [64]
    float* sC2  = sA2 + 64;         // [64]
    float* sB2  = sC2 + 64;         // [16]
    float* sScal= sB2 + 16;         // [4]
    int*   sIdx = (int*)(sScal + 4);// [32]

    int tid = threadIdx.x;
    int bn  = blockIdx.x;
    int bB  = bn >> 11;
    int nn  = bn & (Nn - 1);

    for (int i = tid; i < 9*HP; i += 256) {
        int f = i / HP, o = i - f*HP;
        sWr[i] = (o < HID) ? w_e1[(128 + f)*HID + o] : 0.f;
    }
    for (int i = tid; i < HP*16; i += 256)
        sW2[i] = (i < HID*16) ? w_e2[i] : 0.f;
    for (int i = tid; i < HP; i += 256) sB1[i] = (i < HID) ? b_e1[i] : 0.f;
    for (int i = tid; i < 4*HP; i += 256) sQ1[i] = q1[(long)bn*4*HP + i];
    for (int i = tid; i < 1024; i += 256) { sA1[i] = w_a1[i]; sC1[i] = w_c1[i]; }
    if (tid < 64) { sBa[tid] = b_a1[tid]; sBc[tid] = b_c1[tid];
                    sA2[tid] = w_a2[tid]; sC2[tid] = w_c2[tid]; }
    if (tid < 16) sB2[tid] = b_e2[tid];
    if (tid == 0) { sScal[0] = b_a2[0]; sScal[1] = b_c2[0]; }
    if (tid < 32) sIdx[tid] = nbhd[bn*Jj + tid];
    __syncthreads();

    int w = tid >> 5, lane = tid & 31;
    int qq = lane >> 3, s = lane & 7;
    int j = w*4 + qq;
    int idx = sIdx[j];
    long krow = ((long)(bB*Nn + idx)*4) * HP;

    // rel_enc via 8-lane split (scalar)
    float dx = coors[bn*3+0] - coors[(bB*Nn+idx)*3+0];
    float dy = coors[bn*3+1] - coors[(bB*Nn+idx)*3+1];
    float dz = coors[bn*3+2] - coors[(bB*Nn+idx)*3+2];
    float x = dx*dx + dy*dy + dz*dz;
    float xs = x / (float)(1 << (s & 3));
    float sv = sinf(xs), cv = cosf(xs);
    float myre = (s < 4) ? sv : cv;
    float re[9];
    #pragma unroll
    for (int f = 0; f < 8; f++) re[f] = __shfl_sync(0xffffffffu, myre, f, 8);
    re[8] = x;

    ull acc2[4][8];
    #pragma unroll
    for (int h = 0; h < 4; h++)
        #pragma unroll
        for (int t2 = 0; t2 < 8; t2++) acc2[h][t2] = pack2(0.f, 0.f);

    #pragma unroll 1
    for (int r = 0; r < 9; r++) {
        int i0 = (s + 8*r) * 4;
        // r1 chunk (scalar FFMA, low reg pressure)
        float4 r1v = *(float4*)&sB1[i0];
        #pragma unroll
        for (int f = 0; f < 9; f++) {
            float4 wv = *(float4*)&sWr[f*HP + i0];
            r1v.x += re[f]*wv.x; r1v.y += re[f]*wv.y;
            r1v.z += re[f]*wv.z; r1v.w += re[f]*wv.w;
        }
        ull r1a = pack2(r1v.x, r1v.y);
        ull r1b = pack2(r1v.z, r1v.w);

        // hv scalars for 4 heads x 4 i (packed adds, scalar relu)
        float hvs[4][4];
        #pragma unroll
        for (int h = 0; h < 4; h++) {
            ulonglong2 q2 = *(ulonglong2*)&sQ1[h*HP + i0];
            ulonglong2 k2 = *(const ulonglong2*)&k1[krow + h*HP + i0];
            ull s01 = add2(add2(q2.x, k2.x), r1a);
            ull s23 = add2(add2(q2.y, k2.y), r1b);
            float h0,h1,h2,h3;
            unpack2(s01, h0, h1);
            unpack2(s23, h2, h3);
            hvs[h][0] = fmaxf(h0, 0.f); hvs[h][1] = fmaxf(h1, 0.f);
            hvs[h][2] = fmaxf(h2, 0.f); hvs[h][3] = fmaxf(h3, 0.f);
        }
        // layer2: per i, W2 row loaded once, reused by 4 heads (fma2 over t-pairs)
        #pragma unroll
        for (int ii = 0; ii < 4; ii++) {
            const ulonglong2* w2r = (const ulonglong2*)&sW2[(i0 + ii)*16];
            ulonglong2 wv0 = w2r[0], wv1 = w2r[1], wv2 = w2r[2], wv3 = w2r[3];
            #pragma unroll
            for (int h = 0; h < 4; h++) {
                ull hb = pack2(hvs[h][ii], hvs[h][ii]);
                acc2[h][0] = fma2(hb, wv0.x, acc2[h][0]);
                acc2[h][1] = fma2(hb, wv0.y, acc2[h][1]);
                acc2[h][2] = fma2(hb, wv1.x, acc2[h][2]);
                acc2[h][3] = fma2(hb, wv1.y, acc2[h][3]);
                acc2[h][4] = fma2(hb, wv2.x, acc2[h][4]);
                acc2[h][5] = fma2(hb, wv2.y, acc2[h][5]);
                acc2[h][6] = fma2(hb, wv3.x, acc2[h][6]);
                acc2[h][7] = fma2(hb, wv3.y, acc2[h][7]);
            }
        }
    }

    // butterfly reduce over 8-lane group (packed adds)
    #pragma unroll
    for (int h = 0; h < 4; h++)
        #pragma unroll
        for (int t2 = 0; t2 < 8; t2++) {
            ull v = acc2[h][t2];
            v = add2(v, __shfl_xor_sync(0xffffffffu, v, 1));
            v = add2(v, __shfl_xor_sync(0xffffffffu, v, 2));
            v = add2(v, __shfl_xor_sync(0xffffffffu, v, 4));
            acc2[h][t2] = v;
        }

    // branch task per lane: h = s>>1, br = s&1 (acc2 dead after this point -> mvp reuses regs)
    int hh = s >> 1, br = s & 1;
    ull mvp[16];
    #pragma unroll
    for (int t2 = 0; t2 < 8; t2++) {
        ull v01 = (hh & 1) ? acc2[1][t2] : acc2[0][t2];
        ull v23 = (hh & 1) ? acc2[3][t2] : acc2[2][t2];
        ull v = (hh & 2) ? v23 : v01;
        float m0, m1;
        unpack2(v, m0, m1);
        m0 = fmaxf(m0 + sB2[2*t2],   0.f);
        m1 = fmaxf(m1 + sB2[2*t2+1], 0.f);
        mvp[2*t2]   = pack2(m0, m0);
        mvp[2*t2+1] = pack2(m1, m1);
    }
    const float* w1 = br ? sC1 : sA1;
    const float* w2 = br ? sC2 : sA2;
    const float* bb = br ? sBc : sBa;
    ull dacc = pack2(0.f, 0.f);
    #pragma unroll 2
    for (int u4 = 0; u4 < 16; u4++) {
        ulonglong2 hv = *(const ulonglong2*)&bb[u4*4];
        ull h01 = hv.x, h23 = hv.y;
        #pragma unroll
        for (int t = 0; t < 16; t++) {
            ulonglong2 wv = *(const ulonglong2*)&w1[t*64 + u4*4];
            h01 = fma2(mvp[t], wv.x, h01);
            h23 = fma2(mvp[t], wv.y, h23);
        }
        float a0,a1,a2b,a3;
        unpack2(h01, a0, a1);
        unpack2(h23, a2b, a3);
        a0 = fmaxf(a0, 0.f); a1 = fmaxf(a1, 0.f);
        a2b = fmaxf(a2b, 0.f); a3 = fmaxf(a3, 0.f);
        ulonglong2 w2v = *(const ulonglong2*)&w2[u4*4];
        dacc = fma2(pack2(a0, a1),  w2v.x, dacc);
        dacc = fma2(pack2(a2b, a3), w2v.y, dacc);
    }
    float d0, d1;
    unpack2(dacc, d0, d1);
    float bacc = d0 + d1;

    long e = ((long)(bB*Hh + hh)*Nn + nn)*Jj + j;
    float val = bacc + (br ? sScal[1] : sScal[0]);
    (br ? cwo : simo)[e] = val;
}

// ---------------- softmax over j, out = attn@v_nb, coors_out ----------------
__global__ void attend_kernel(const float* __restrict__ qkv,
                              const float* __restrict__ simi, const float* __restrict__ cwi,
                              const int* __restrict__ nbhd, const float* __restrict__ basis,
                              float* __restrict__ outh, float* __restrict__ coors_out)
{
    int bn = blockIdx.x;
    int b = bn / Nn, n = bn % Nn;
    int w = threadIdx.x >> 5, lane = threadIdx.x & 31;
    int idx = nbhd[bn*Jj + lane];

    float s = simi[((long)((b*Hh + w)*Nn + n))*Jj + lane];
    float mx = s;
    #pragma unroll
    for (int o = 16; o; o >>= 1) mx = fmaxf(mx, __shfl_xor_sync(0xffffffffu, mx, o));
    float e = expf(s - mx);
    float sum = e;
    #pragma unroll
    for (int o = 16; o; o >>= 1) sum += __shfl_xor_sync(0xffffffffu, sum, o);
    float attn = e / sum;

    float acc0 = 0.f, acc1 = 0.f;
    #pragma unroll
    for (int j = 0; j < Jj; j++) {
        float a = __shfl_sync(0xffffffffu, attn, j);
        int ij  = __shfl_sync(0xffffffffu, idx,  j);
        const float* vr = qkv + (long)(b*Nn + ij)*QKVC + 2*Hh*DHd + w*DHd;
        acc0 += a * vr[lane];
        acc1 += a * vr[lane + 32];
    }
    outh[(long)bn*Dd + w*DHd + lane]      = acc0;
    outh[(long)bn*Dd + w*DHd + lane + 32] = acc1;

    if (w == 0) {
        float cwt = 0.f;
        #pragma unroll
        for (int hh = 0; hh < Hh; hh++)
            cwt += cwi[((long)((b*Hh + hh)*Nn + n))*Jj + lane];
        const float* brow = basis + ((long)(b*Nn + n)*Nn + idx)*3;
        float cx = cwt*brow[0], cy = cwt*brow[1], cz = cwt*brow[2];
        #pragma unroll
        for (int o = 16; o; o >>= 1) {
            cx += __shfl_xor_sync(0xffffffffu, cx, o);
            cy += __shfl_xor_sync(0xffffffffu, cy, o);
            cz += __shfl_xor_sync(0xffffffffu, cz, o);
        }
        if (lane == 0) {
            coors_out[bn*3+0] = cx;
            coors_out[bn*3+1] = cy;
            coors_out[bn*3+2] = cz;
        }
    }
}

// ---------------- launch ----------------
extern "C" void kernel_launch(void* const* d_in, const int* in_sizes, int n_in,
                              void* d_out, int out_size)
{
    const float* feats  = (const float*)d_in[0];
    const float* coors  = (const float*)d_in[1];
    const float* basis  = (const float*)d_in[2];
    const int*   nbhd   = (const int*)  d_in[3];
    const float* w_qkv  = (const float*)d_in[4];
    const float* w_out  = (const float*)d_in[5];
    const float* b_out  = (const float*)d_in[6];
    const float* w_e1   = (const float*)d_in[7];
    const float* b_e1   = (const float*)d_in[8];
    const float* w_e2   = (const float*)d_in[9];
    const float* b_e2   = (const float*)d_in[10];
    const float* w_a1   = (const float*)d_in[11];
    const float* b_a1   = (const float*)d_in[12];
    const float* w_a2   = (const float*)d_in[13];
    const float* b_a2   = (const float*)d_in[14];
    const float* w_c1   = (const float*)d_in[15];
    const float* b_c1   = (const float*)d_in[16];
    const float* w_c2   = (const float*)d_in[17];
    const float* b_c2   = (const float*)d_in[18];

    float* out       = (float*)d_out;
    float* coors_out = out + (long)Bq*Nn*Dd;

    void* p;
    cudaGetSymbolAddress(&p, g_qkv);  float* qkv  = (float*)p;
    cudaGetSymbolAddress(&p, g_q1);   float* q1   = (float*)p;
    cudaGetSymbolAddress(&p, g_k1);   float* k1   = (float*)p;
    cudaGetSymbolAddress(&p, g_sim);  float* simv = (float*)p;
    cudaGetSymbolAddress(&p, g_cw);   float* cwv  = (float*)p;
    cudaGetSymbolAddress(&p, g_outh); float* outh = (float*)p;

    // 1) qkv = feats @ w_qkv
    gemm_tile<<<dim3(QKVC/64, (Bq*Nn)/64), 256>>>(feats, w_qkv, nullptr, qkv,
                                                  Bq*Nn, QKVC, Dd);

    // 2) q1/k1 tables
    const int smemQK = (64*HP*2 + 16*256*2) * 4;
    cudaFuncSetAttribute(qk1_kernel, cudaFuncAttributeMaxDynamicSharedMemorySize, smemQK);
    qk1_kernel<<<256, 256, smemQK>>>(qkv, w_e1, q1, k1);

    // 3) edge_flat
    const int smemE = (9*HP + HP*16 + HP + 4*HP + 1024 + 1024 + 64*4 + 16 + 4 + 32) * 4;
    cudaFuncSetAttribute(edge_flat, cudaFuncAttributeMaxDynamicSharedMemorySize, smemE);
    edge_flat<<<NODES, 256, smemE>>>(q1, k1, coors, nbhd,
        w_e1, b_e1, w_e2, b_e2, w_a1, b_a1, w_a2, b_a2, w_c1, b_c1, w_c2, b_c2,
        simv, cwv);

    // 4) softmax + v-gather + coors einsum
    attend_kernel<<<Bq*Nn, 128>>>(qkv, simv, cwv, nbhd, basis, outh, coors_out);

    // 5) out = outh @ w_out + b_out
    gemm_tile<<<dim3(Dd/64, (Bq*Nn)/64), 256>>>(outh, w_out, b_out, out,
                                                Bq*Nn, Dd, Dd);
}

// round 6
// speedup vs baseline: 1.8284x; 1.7513x over previous
#include <cuda_runtime.h>
#include <math.h>

#define Bq   2
#define Nn   2048
#define Dd   256
#define Hh   4
#define DHd  64
#define Jj   32
#define FFf  4
#define Mm   16
#define HID  274
#define HP   288            // padded hidden dim (cols 274..287 zero)
#define W2S  292            // sW2t row stride (floats)
#define QKVC (3*Hh*DHd)     // 768
#define NODES (Bq*Nn)       // 4096

// ---------------- scratch ----------------
__device__ float g_qkv [Bq*Nn*QKVC];
__device__ float g_q1  [Bq*Nn*Hh*HP];
__device__ float g_k1  [Bq*Nn*Hh*HP];
__device__ float g_sim [Bq*Hh*Nn*Jj];
__device__ float g_cw  [Bq*Hh*Nn*Jj];
__device__ float g_outh[Bq*Nn*Dd];

// ---------------- generic 64x64 tiled SGEMM, C = A@B (+bias) ----------------
__global__ void gemm_tile(const float* __restrict__ A, const float* __restrict__ Bm,
                          const float* __restrict__ bias, float* __restrict__ C,
                          int M, int N, int K)
{
    __shared__ float As[16][65];
    __shared__ float Bs[16][65];
    int tid = threadIdx.x;
    int tx = tid & 15, ty = tid >> 4;
    int rowBase = blockIdx.y * 64;
    int colBase = blockIdx.x * 64;
    float acc[4][4] = {};
    for (int k0 = 0; k0 < K; k0 += 16) {
        for (int i = tid; i < 1024; i += 256) {
            int r = i >> 4, kk = i & 15;
            As[kk][r] = A[(long)(rowBase + r) * K + k0 + kk];
        }
        for (int i = tid; i < 1024; i += 256) {
            int kk = i >> 6, c = i & 63;
            Bs[kk][c] = Bm[(long)(k0 + kk) * N + colBase + c];
        }
        __syncthreads();
        #pragma unroll
        for (int kk = 0; kk < 16; kk++) {
            float a[4], bb[4];
            #pragma unroll
            for (int r = 0; r < 4; r++) a[r] = As[kk][ty*4 + r];
            #pragma unroll
            for (int c = 0; c < 4; c++) bb[c] = Bs[kk][tx*4 + c];
            #pragma unroll
            for (int r = 0; r < 4; r++)
                #pragma unroll
                for (int c = 0; c < 4; c++)
                    acc[r][c] += a[r] * bb[c];
        }
        __syncthreads();
    }
    #pragma unroll
    for (int r = 0; r < 4; r++) {
        int row = rowBase + ty*4 + r;
        #pragma unroll
        for (int c = 0; c < 4; c++) {
            int col = colBase + tx*4 + c;
            float v = acc[r][c];
            if (bias) v += bias[col];
            C[(long)row * N + col] = v;
        }
    }
}

// ---------------- q1/k1 precompute: row (node*4+h) = q_h(node) @ W1q ----------------
__global__ void __launch_bounds__(256,1) qk1_kernel(
    const float* __restrict__ qkv, const float* __restrict__ w_e1,
    float* __restrict__ q1, float* __restrict__ k1)
{
    extern __shared__ float sm[];
    float* sWq = sm;             // [64][HP]
    float* sWk = sWq + 64*HP;    // [64][HP]
    float* sAq = sWk + 64*HP;    // [16][256]
    float* sAk = sAq + 16*256;   // [16][256]
    int tid = threadIdx.x;
    int node0 = blockIdx.x * 16;

    for (int i = tid; i < 64*HP; i += 256) {
        int r = i / HP, o = i - r*HP;
        sWq[i] = (o < HID) ? w_e1[r*HID + o] : 0.f;
        sWk[i] = (o < HID) ? w_e1[(64 + r)*HID + o] : 0.f;
    }
    for (int i = tid; i < 4096; i += 256) {
        int t = i >> 8, c = i & 255;
        sAq[i] = qkv[(long)(node0 + t)*QKVC + c];
        sAk[i] = qkv[(long)(node0 + t)*QKVC + 256 + c];
    }
    __syncthreads();

    int ty = tid >> 4, tx = tid & 15;
    for (int pass = 0; pass < 2; pass++) {
        const float* A = pass ? sAk : sAq;
        const float* W = pass ? sWk : sWq;
        float* Cg = pass ? k1 : q1;
        float acc[4][18];
        #pragma unroll
        for (int r = 0; r < 4; r++)
            #pragma unroll
            for (int c = 0; c < 18; c++) acc[r][c] = 0.f;
        #pragma unroll 4
        for (int i = 0; i < 64; i++) {
            float a[4];
            #pragma unroll
            for (int r = 0; r < 4; r++) a[r] = A[ty*256 + r*64 + i];
            #pragma unroll
            for (int c = 0; c < 18; c++) {
                float w = W[i*HP + tx + 16*c];
                #pragma unroll
                for (int r = 0; r < 4; r++) acc[r][c] += a[r] * w;
            }
        }
        #pragma unroll
        for (int r = 0; r < 4; r++) {
            long grow = (long)(node0 + ty)*4 + r;
            #pragma unroll
            for (int c = 0; c < 18; c++)
                Cg[grow*HP + tx + 16*c] = acc[r][c];
        }
    }
}

// ---------------- edge_flat: warp = (node, j-quad), all 4 heads; no barriers ----------------
__global__ void __launch_bounds__(256, 2) edge_flat(
    const float* __restrict__ q1, const float* __restrict__ k1,
    const float* __restrict__ coors, const int* __restrict__ nbhd,
    const float* __restrict__ w_e1, const float* __restrict__ b_e1,
    const float* __restrict__ w_e2, const float* __restrict__ b_e2,
    const float* __restrict__ w_a1, const float* __restrict__ b_a1,
    const float* __restrict__ w_a2, const float* __restrict__ b_a2,
    const float* __restrict__ w_c1, const float* __restrict__ b_c1,
    const float* __restrict__ w_c2, const float* __restrict__ b_c2,
    float* __restrict__ simo, float* __restrict__ cwo)
{
    extern __shared__ float sm[];
    float* sWr  = sm;               // [9][HP]
    float* sW2t = sWr + 9*HP;       // [16][W2S]  (transposed w_e2)
    float* sB1  = sW2t + 16*W2S;    // [HP]
    float* sQ1  = sB1 + HP;         // [4][HP]
    float* sA1  = sQ1 + 4*HP;       // [16][64]
    float* sC1  = sA1 + 1024;       // [16][64]
    float* sBa  = sC1 + 1024;       // [64]
    float* sBc  = sBa + 64;         // [64]
    float* sA2  = sBc + 64;         // [64]
    float* sC2  = sA2 + 64;         // [64]
    float* sB2  = sC2 + 64;         // [16]
    float* sScal= sB2 + 16;         // [4]
    int*   sIdx = (int*)(sScal + 4);// [32]

    int tid = threadIdx.x;
    int bn  = blockIdx.x;
    int bB  = bn >> 11;
    int nn  = bn & (Nn - 1);

    for (int i = tid; i < 9*HP; i += 256) {
        int f = i / HP, o = i - f*HP;
        sWr[i] = (o < HID) ? w_e1[(128 + f)*HID + o] : 0.f;
    }
    for (int i = tid; i < 16*W2S; i += 256) {
        int t = i / W2S, o = i - t*W2S;
        sW2t[i] = (o < HID) ? w_e2[o*16 + t] : 0.f;
    }
    for (int i = tid; i < HP; i += 256) sB1[i] = (i < HID) ? b_e1[i] : 0.f;
    for (int i = tid; i < 4*HP; i += 256) sQ1[i] = q1[(long)bn*4*HP + i];
    for (int i = tid; i < 1024; i += 256) { sA1[i] = w_a1[i]; sC1[i] = w_c1[i]; }
    if (tid < 64) { sBa[tid] = b_a1[tid]; sBc[tid] = b_c1[tid];
                    sA2[tid] = w_a2[tid]; sC2[tid] = w_c2[tid]; }
    if (tid < 16) sB2[tid] = b_e2[tid];
    if (tid == 0) { sScal[0] = b_a2[0]; sScal[1] = b_c2[0]; }
    if (tid < 32) sIdx[tid] = nbhd[bn*Jj + tid];
    __syncthreads();

    int w = tid >> 5, lane = tid & 31;
    int qq = lane >> 3, s = lane & 7;
    int j = w*4 + qq;
    int idx = sIdx[j];
    long krow = ((long)(bB*Nn + idx)*4) * HP;

    // rel_enc: lanes s=0..3 -> sin(x/2^s), s=4..7 -> cos(x/2^(s-4))
    float dx = coors[bn*3+0] - coors[(bB*Nn+idx)*3+0];
    float dy = coors[bn*3+1] - coors[(bB*Nn+idx)*3+1];
    float dz = coors[bn*3+2] - coors[(bB*Nn+idx)*3+2];
    float x = dx*dx + dy*dy + dz*dz;
    float xs = x / (float)(1 << (s & 3));
    float sv = sinf(xs), cv = cosf(xs);
    float myre = (s < 4) ? sv : cv;
    float re[9];
    #pragma unroll
    for (int f = 0; f < 8; f++) re[f] = __shfl_sync(0xffffffffu, myre, f, 8);
    re[8] = x;

    float acc[4][16];
    #pragma unroll
    for (int h = 0; h < 4; h++)
        #pragma unroll
        for (int t = 0; t < 16; t++) acc[h][t] = 0.f;

    #pragma unroll 3
    for (int r = 0; r < 9; r++) {
        int i0 = (s + 8*r) * 4;
        // k1 global loads issued first (12 independent LDG.128 per unroll window)
        float4 k4[4];
        #pragma unroll
        for (int h = 0; h < 4; h++)
            k4[h] = *(const float4*)&k1[krow + h*HP + i0];
        // r1 chunk
        float4 r1v = *(float4*)&sB1[i0];
        #pragma unroll
        for (int f = 0; f < 9; f++) {
            float4 wv = *(float4*)&sWr[f*HP + i0];
            r1v.x += re[f]*wv.x; r1v.y += re[f]*wv.y;
            r1v.z += re[f]*wv.z; r1v.w += re[f]*wv.w;
        }
        // h chunks, 4 heads
        float4 hv[4];
        #pragma unroll
        for (int h = 0; h < 4; h++) {
            float4 q4 = *(float4*)&sQ1[h*HP + i0];
            hv[h].x = fmaxf(q4.x + k4[h].x + r1v.x, 0.f);
            hv[h].y = fmaxf(q4.y + k4[h].y + r1v.y, 0.f);
            hv[h].z = fmaxf(q4.z + k4[h].z + r1v.z, 0.f);
            hv[h].w = fmaxf(q4.w + k4[h].w + r1v.w, 0.f);
        }
        // layer2: W2 row chunk loaded once, used by all 4 heads
        #pragma unroll
        for (int t = 0; t < 16; t++) {
            float4 wv = *(float4*)&sW2t[t*W2S + i0];
            #pragma unroll
            for (int h = 0; h < 4; h++)
                acc[h][t] += hv[h].x*wv.x + hv[h].y*wv.y
                           + hv[h].z*wv.z + hv[h].w*wv.w;
        }
    }

    // butterfly reduce over 8-lane group
    #pragma unroll
    for (int h = 0; h < 4; h++)
        #pragma unroll
        for (int t = 0; t < 16; t++) {
            float v = acc[h][t];
            v += __shfl_xor_sync(0xffffffffu, v, 1);
            v += __shfl_xor_sync(0xffffffffu, v, 2);
            v += __shfl_xor_sync(0xffffffffu, v, 4);
            acc[h][t] = v;
        }

    // branch task per lane: h = s>>1, br = s&1
    int hh = s >> 1, br = s & 1;
    float mv[16];
    #pragma unroll
    for (int t = 0; t < 16; t++) {
        float v01 = (hh & 1) ? acc[1][t] : acc[0][t];
        float v23 = (hh & 1) ? acc[3][t] : acc[2][t];
        float v = (hh & 2) ? v23 : v01;
        mv[t] = fmaxf(v + sB2[t], 0.f);
    }
    const float* w1 = br ? sC1 : sA1;
    const float* w2 = br ? sC2 : sA2;
    const float* bb = br ? sBc : sBa;
    float bacc = 0.f;
    #pragma unroll 4
    for (int u4 = 0; u4 < 16; u4++) {
        float4 hv = *(float4*)&bb[u4*4];
        #pragma unroll
        for (int t = 0; t < 16; t++) {
            float4 wv = *(float4*)&w1[t*64 + u4*4];
            hv.x += mv[t]*wv.x; hv.y += mv[t]*wv.y;
            hv.z += mv[t]*wv.z; hv.w += mv[t]*wv.w;
        }
        float4 w2v = *(float4*)&w2[u4*4];
        bacc += fmaxf(hv.x,0.f)*w2v.x + fmaxf(hv.y,0.f)*w2v.y
              + fmaxf(hv.z,0.f)*w2v.z + fmaxf(hv.w,0.f)*w2v.w;
    }
    long e = ((long)(bB*Hh + hh)*Nn + nn)*Jj + j;
    float val = bacc + (br ? sScal[1] : sScal[0]);
    (br ? cwo : simo)[e] = val;
}

// ---------------- softmax over j, out = attn@v_nb, coors_out ----------------
__global__ void attend_kernel(const float* __restrict__ qkv,
                              const float* __restrict__ simi, const float* __restrict__ cwi,
                              const int* __restrict__ nbhd, const float* __restrict__ basis,
                              float* __restrict__ outh, float* __restrict__ coors_out)
{
    int bn = blockIdx.x;
    int b = bn / Nn, n = bn % Nn;
    int w = threadIdx.x >> 5, lane = threadIdx.x & 31;
    int idx = nbhd[bn*Jj + lane];

    float s = simi[((long)((b*Hh + w)*Nn + n))*Jj + lane];
    float mx = s;
    #pragma unroll
    for (int o = 16; o; o >>= 1) mx = fmaxf(mx, __shfl_xor_sync(0xffffffffu, mx, o));
    float e = expf(s - mx);
    float sum = e;
    #pragma unroll
    for (int o = 16; o; o >>= 1) sum += __shfl_xor_sync(0xffffffffu, sum, o);
    float attn = e / sum;

    float acc0 = 0.f, acc1 = 0.f;
    #pragma unroll
    for (int j = 0; j < Jj; j++) {
        float a = __shfl_sync(0xffffffffu, attn, j);
        int ij  = __shfl_sync(0xffffffffu, idx,  j);
        const float* vr = qkv + (long)(b*Nn + ij)*QKVC + 2*Hh*DHd + w*DHd;
        acc0 += a * vr[lane];
        acc1 += a * vr[lane + 32];
    }
    outh[(long)bn*Dd + w*DHd + lane]      = acc0;
    outh[(long)bn*Dd + w*DHd + lane + 32] = acc1;

    if (w == 0) {
        float cwt = 0.f;
        #pragma unroll
        for (int hh = 0; hh < Hh; hh++)
            cwt += cwi[((long)((b*Hh + hh)*Nn + n))*Jj + lane];
        const float* brow = basis + ((long)(b*Nn + n)*Nn + idx)*3;
        float cx = cwt*brow[0], cy = cwt*brow[1], cz = cwt*brow[2];
        #pragma unroll
        for (int o = 16; o; o >>= 1) {
            cx += __shfl_xor_sync(0xffffffffu, cx, o);
            cy += __shfl_xor_sync(0xffffffffu, cy, o);
            cz += __shfl_xor_sync(0xffffffffu, cz, o);
        }
        if (lane == 0) {
            coors_out[bn*3+0] = cx;
            coors_out[bn*3+1] = cy;
            coors_out[bn*3+2] = cz;
        }
    }
}

// ---------------- launch ----------------
extern "C" void kernel_launch(void* const* d_in, const int* in_sizes, int n_in,
                              void* d_out, int out_size)
{
    const float* feats  = (const float*)d_in[0];
    const float* coors  = (const float*)d_in[1];
    const float* basis  = (const float*)d_in[2];
    const int*   nbhd   = (const int*)  d_in[3];
    const float* w_qkv  = (const float*)d_in[4];
    const float* w_out  = (const float*)d_in[5];
    const float* b_out  = (const float*)d_in[6];
    const float* w_e1   = (const float*)d_in[7];
    const float* b_e1   = (const float*)d_in[8];
    const float* w_e2   = (const float*)d_in[9];
    const float* b_e2   = (const float*)d_in[10];
    const float* w_a1   = (const float*)d_in[11];
    const float* b_a1   = (const float*)d_in[12];
    const float* w_a2   = (const float*)d_in[13];
    const float* b_a2   = (const float*)d_in[14];
    const float* w_c1   = (const float*)d_in[15];
    const float* b_c1   = (const float*)d_in[16];
    const float* w_c2   = (const float*)d_in[17];
    const float* b_c2   = (const float*)d_in[18];

    float* out       = (float*)d_out;
    float* coors_out = out + (long)Bq*Nn*Dd;

    void* p;
    cudaGetSymbolAddress(&p, g_qkv);  float* qkv  = (float*)p;
    cudaGetSymbolAddress(&p, g_q1);   float* q1   = (float*)p;
    cudaGetSymbolAddress(&p, g_k1);   float* k1   = (float*)p;
    cudaGetSymbolAddress(&p, g_sim);  float* simv = (float*)p;
    cudaGetSymbolAddress(&p, g_cw);   float* cwv  = (float*)p;
    cudaGetSymbolAddress(&p, g_outh); float* outh = (float*)p;

    // 1) qkv = feats @ w_qkv
    gemm_tile<<<dim3(QKVC/64, (Bq*Nn)/64), 256>>>(feats, w_qkv, nullptr, qkv,
                                                  Bq*Nn, QKVC, Dd);

    // 2) q1/k1 tables
    const int smemQK = (64*HP*2 + 16*256*2) * 4;
    cudaFuncSetAttribute(qk1_kernel, cudaFuncAttributeMaxDynamicSharedMemorySize, smemQK);
    qk1_kernel<<<256, 256, smemQK>>>(qkv, w_e1, q1, k1);

    // 3) edge_flat
    const int smemE = (9*HP + 16*W2S + HP + 4*HP + 1024 + 1024 + 64*4 + 16 + 4 + 32) * 4;
    cudaFuncSetAttribute(edge_flat, cudaFuncAttributeMaxDynamicSharedMemorySize, smemE);
    edge_flat<<<NODES, 256, smemE>>>(q1, k1, coors, nbhd,
        w_e1, b_e1, w_e2, b_e2, w_a1, b_a1, w_a2, b_a2, w_c1, b_c1, w_c2, b_c2,
        simv, cwv);

    // 4) softmax + v-gather + coors einsum
    attend_kernel<<<Bq*Nn, 128>>>(qkv, simv, cwv, nbhd, basis, outh, coors_out);

    // 5) out = outh @ w_out + b_out
    gemm_tile<<<dim3(Dd/64, (Bq*Nn)/64), 256>>>(outh, w_out, b_out, out,
                                                Bq*Nn, Dd, Dd);
}